// round 14
// baseline (speedup 1.0000x reference)
#include <cuda_runtime.h>
#include <cuda_fp16.h>
#include <cstdint>

// out = norm @ ((norm^T @ x) @ W),  norm = x / max(||x_row||, 1e-12)
// y = sqrt(inv)*x  =>  G = y^T @ y (symmetric).
// fp16 hi/lo split GEMMs on m16n8k16 HMMA (fp32 acc).
// GEMM1/2: two passes (ah*bh + ah*bl). GEMM3: single pass (H hi only) —
// legacy-HMMA rate ceiling means fewer MMAs is the only remaining lever.

#define NROWS 8192
#define DIM   1024
typedef __half f16;

// ---------------- scratch (device globals; no allocation allowed) ----------
__device__ float g_inv[NROWS];
__device__ f16 g_nh[NROWS * DIM];                       // norm hi, row-major
__device__ f16 g_yh[DIM * NROWS], g_yl[DIM * NROWS];    // y^T hi/lo [1024,8192]
__device__ f16 g_wh[DIM * DIM];                         // W^T hi
__device__ f16 g_gh[DIM * DIM],  g_gl[DIM * DIM];       // G hi/lo
__device__ f16 g_hh[DIM * DIM],  g_hl[DIM * DIM];       // H^T hi/lo
__device__ float g_P[8 * DIM * DIM];                    // split-K partials

__constant__ int2 c_tri[36] = {
    {0,0},{1,0},{1,1},{2,0},{2,1},{2,2},{3,0},{3,1},{3,2},{3,3},
    {4,0},{4,1},{4,2},{4,3},{4,4},{5,0},{5,1},{5,2},{5,3},{5,4},
    {5,5},{6,0},{6,1},{6,2},{6,3},{6,4},{6,5},{6,6},{7,0},{7,1},
    {7,2},{7,3},{7,4},{7,5},{7,6},{7,7}
};

// ---------------- PTX helpers ----------------------------------------------
__device__ __forceinline__ uint32_t smem_u32(const void* p) {
    uint32_t a;
    asm("{ .reg .u64 t; cvta.to.shared.u64 t, %1; cvt.u32.u64 %0, t; }" : "=r"(a) : "l"(p));
    return a;
}

#define CP16(saddr, gptr) \
    asm volatile("cp.async.cg.shared.global [%0], [%1], 16;" :: "r"(saddr), "l"(gptr))
#define CP_COMMIT() asm volatile("cp.async.commit_group;" ::: "memory")
#define CP_WAIT(n)  asm volatile("cp.async.wait_group %0;" :: "n"(n) : "memory")

#define LDSM4(r, addr) \
    asm volatile("ldmatrix.sync.aligned.m8n8.x4.shared.b16 {%0,%1,%2,%3}, [%4];" \
        : "=r"((r)[0]), "=r"((r)[1]), "=r"((r)[2]), "=r"((r)[3]) : "r"(addr))

#define MMA(c, a, b) \
    asm volatile("mma.sync.aligned.m16n8k16.row.col.f32.f16.f16.f32 " \
        "{%0,%1,%2,%3}, {%4,%5,%6,%7}, {%8,%9}, {%0,%1,%2,%3};" \
        : "+f"((c)[0]), "+f"((c)[1]), "+f"((c)[2]), "+f"((c)[3]) \
        : "r"((a)[0]), "r"((a)[1]), "r"((a)[2]), "r"((a)[3]), "r"((b)[0]), "r"((b)[1]))

// ---------------- small kernels --------------------------------------------
__global__ void rownorm_inv(const float* __restrict__ x, float* __restrict__ inv) {
    const int row = blockIdx.x;
    float4 v = reinterpret_cast<const float4*>(x + (size_t)row * DIM)[threadIdx.x];
    float s = v.x * v.x + v.y * v.y + v.z * v.z + v.w * v.w;
    #pragma unroll
    for (int o = 16; o > 0; o >>= 1) s += __shfl_down_sync(0xFFFFFFFFu, s, o);
    __shared__ float ws[8];
    if ((threadIdx.x & 31) == 0) ws[threadIdx.x >> 5] = s;
    __syncthreads();
    if (threadIdx.x == 0) {
        float t = 0.f;
        #pragma unroll
        for (int i = 0; i < 8; i++) t += ws[i];
        inv[row] = 1.0f / fmaxf(sqrtf(t), 1e-12f);
    }
}

__device__ __forceinline__ void split_h(float v, f16& h, f16& l) {
    h = __float2half_rn(v);
    l = __float2half_rn(v - __half2float(h));
}

__global__ void conv_x(const float* __restrict__ x, const float* __restrict__ inv,
                       f16* __restrict__ nh,
                       f16* __restrict__ yh, f16* __restrict__ yl) {
    __shared__ float sy[32][33];
    const int c = blockIdx.x * 32 + threadIdx.x;
    const int r0 = blockIdx.y * 32;
    #pragma unroll
    for (int i = 0; i < 4; i++) {
        int rl = threadIdx.y + i * 8;
        int r = r0 + rl;
        float iv = inv[r];
        float v = x[(size_t)r * DIM + c];
        nh[(size_t)r * DIM + c] = __float2half_rn(v * iv);
        sy[rl][threadIdx.x] = v * sqrtf(iv);
    }
    __syncthreads();
    const int tr = r0 + threadIdx.x;
    #pragma unroll
    for (int i = 0; i < 4; i++) {
        int cl = threadIdx.y + i * 8;
        int tc = blockIdx.x * 32 + cl;
        f16 h, l;
        split_h(sy[threadIdx.x][cl], h, l);
        yh[(size_t)tc * NROWS + tr] = h;
        yl[(size_t)tc * NROWS + tr] = l;
    }
}

__global__ void conv_w(const float* __restrict__ w, f16* __restrict__ wh) {
    __shared__ float sw[32][33];
    const int c = blockIdx.x * 32 + threadIdx.x;
    const int r0 = blockIdx.y * 32;
    #pragma unroll
    for (int i = 0; i < 4; i++) {
        int rl = threadIdx.y + i * 8;
        sw[rl][threadIdx.x] = w[(size_t)(r0 + rl) * DIM + c];
    }
    __syncthreads();
    const int tr = r0 + threadIdx.x;
    #pragma unroll
    for (int i = 0; i < 4; i++) {
        int cl = threadIdx.y + i * 8;
        int tc = blockIdx.x * 32 + cl;
        wh[(size_t)tc * DIM + tr] = __float2half_rn(sw[threadIdx.x][cl]);
    }
}

__global__ void combine_tri(const float* __restrict__ P, int np,
                            f16* __restrict__ hi, f16* __restrict__ lo) {
    const int2 bp = c_tri[blockIdx.y];
    const int idx = (blockIdx.x * 256 + threadIdx.x) * 4;
    const int R = bp.x * 128 + (idx >> 7);
    const int C = bp.y * 128 + (idx & 127);
    const size_t o = (size_t)R * DIM + C;
    float v[4] = {0.f, 0.f, 0.f, 0.f};
    for (int p = 0; p < np; p++) {
        float4 a = *reinterpret_cast<const float4*>(P + (size_t)p * DIM * DIM + o);
        v[0] += a.x; v[1] += a.y; v[2] += a.z; v[3] += a.w;
    }
    f16 h[4], l[4];
    #pragma unroll
    for (int j = 0; j < 4; j++) split_h(v[j], h[j], l[j]);
    *reinterpret_cast<uint2*>(hi + o) = *reinterpret_cast<const uint2*>(h);
    *reinterpret_cast<uint2*>(lo + o) = *reinterpret_cast<const uint2*>(l);
    if (bp.x != bp.y) {
        #pragma unroll
        for (int j = 0; j < 4; j++) {
            hi[(size_t)(C + j) * DIM + R] = h[j];
            lo[(size_t)(C + j) * DIM + R] = l[j];
        }
    }
}

__global__ void combine_lin(const float* __restrict__ P, int np,
                            f16* __restrict__ hi, f16* __restrict__ lo) {
    const int i = (blockIdx.x * 256 + threadIdx.x) * 4;
    float v[4] = {0.f, 0.f, 0.f, 0.f};
    for (int p = 0; p < np; p++) {
        float4 a = *reinterpret_cast<const float4*>(P + (size_t)p * DIM * DIM + i);
        v[0] += a.x; v[1] += a.y; v[2] += a.z; v[3] += a.w;
    }
    f16 h[4], l[4];
    #pragma unroll
    for (int j = 0; j < 4; j++) split_h(v[j], h[j], l[j]);
    *reinterpret_cast<uint2*>(hi + i) = *reinterpret_cast<const uint2*>(h);
    *reinterpret_cast<uint2*>(lo + i) = *reinterpret_cast<const uint2*>(l);
}

// ---------------- fp16 HMMA GEMM: C[m,n] = sum_k A[m,k]*B[n,k] --------------
// CTA 128x128, BK=32, 4 warps (2m x 2n), warp tile 64x64.
// PASS2=1: Bh+Bl two-pass. PASS2=0: Bh single pass (2 tiles staged, less smem).
#define TILE_PB  10240                // 128 * 80

template <int TRI, int PASS2>
__global__ __launch_bounds__(128, 2)
void gemm_f16(const f16* __restrict__ Ah,
              const f16* __restrict__ Bh, const f16* __restrict__ Bl,
              float* __restrict__ Cbase, size_t cplane,
              int N, int ldk, int ksplit) {
    constexpr int NT = PASS2 ? 3 : 2;             // tiles per stage
    constexpr int STAGE = NT * TILE_PB;
    extern __shared__ char smem[];
    const uint32_t su = smem_u32(smem);
    const int tid = threadIdx.x;
    const int lane = tid & 31;
    const int wid = tid >> 5;
    const int warp_m = wid & 1;
    const int warp_n = wid >> 1;
    int m0, n0;
    if (TRI) {
        const int2 bp = c_tri[blockIdx.x];
        m0 = bp.x * 128; n0 = bp.y * 128;
    } else {
        m0 = blockIdx.y * 128; n0 = blockIdx.x * 128;
    }
    const int k0 = blockIdx.z * ksplit;
    float* C = Cbase + (size_t)blockIdx.z * cplane;

    float acc[4][8][4];
    #pragma unroll
    for (int i = 0; i < 4; i++)
        #pragma unroll
        for (int j = 0; j < 8; j++)
            #pragma unroll
            for (int q = 0; q < 4; q++) acc[i][j][q] = 0.f;

    const uint32_t a_off = (uint32_t)(warp_m * 64 + (lane & 15)) * 80 + ((lane >> 4) << 4);
    const uint32_t b_off = (uint32_t)(warp_n * 64 + ((lane >> 4) << 3) + (lane & 7)) * 80
                         + (((lane >> 3) & 1) << 4);

    // stage loader (局部 lambda-style macro via loop)
    auto stage_load = [&](uint32_t s_stage, int k) {
        #pragma unroll
        for (int i = 0; i < 4; i++) {
            const int idx = tid + i * 128;
            const int row = idx >> 2;
            const int cb = (idx & 3) * 16;
            const uint32_t so = s_stage + row * 80 + cb;
            const size_t goA = ((size_t)(m0 + row) * ldk + k) * 2 + cb;
            const size_t goB = ((size_t)(n0 + row) * ldk + k) * 2 + cb;
            CP16(so,           (const char*)Ah + goA);
            CP16(so + TILE_PB, (const char*)Bh + goB);
            if (PASS2) CP16(so + 2 * TILE_PB, (const char*)Bl + goB);
        }
    };

    const int NIT = ksplit / 32;
    stage_load(su, k0);
    CP_COMMIT();

    for (int it = 0; it < NIT; it++) {
        if (it + 1 < NIT) {
            stage_load(su + ((it + 1) & 1) * STAGE, k0 + (it + 1) * 32);
            CP_COMMIT();
            CP_WAIT(1);
        } else {
            CP_WAIT(0);
        }
        __syncthreads();

        const uint32_t st = su + (it & 1) * STAGE;
        const uint32_t a_h = st + a_off;
        const uint32_t b_h = st + TILE_PB + b_off;
        const uint32_t b_l = b_h + TILE_PB;

        #pragma unroll
        for (int ks = 0; ks < 2; ks++) {
            uint32_t ah[4][4], bb[8][2];
            #pragma unroll
            for (int mf = 0; mf < 4; mf++) LDSM4(ah[mf], a_h + mf * 1280 + ks * 32);
            #pragma unroll
            for (int bg = 0; bg < 4; bg++) {
                uint32_t t[4];
                LDSM4(t, b_h + bg * 1280 + ks * 32);
                bb[2 * bg][0] = t[0]; bb[2 * bg][1] = t[1];
                bb[2 * bg + 1][0] = t[2]; bb[2 * bg + 1][1] = t[3];
            }
            #pragma unroll
            for (int mf = 0; mf < 4; mf++)
                #pragma unroll
                for (int nf = 0; nf < 8; nf++)
                    MMA(acc[mf][nf], ah[mf], bb[nf]);
            if (PASS2) {
                #pragma unroll
                for (int bg = 0; bg < 4; bg++) {
                    uint32_t t[4];
                    LDSM4(t, b_l + bg * 1280 + ks * 32);
                    bb[2 * bg][0] = t[0]; bb[2 * bg][1] = t[1];
                    bb[2 * bg + 1][0] = t[2]; bb[2 * bg + 1][1] = t[3];
                }
                #pragma unroll
                for (int mf = 0; mf < 4; mf++)
                    #pragma unroll
                    for (int nf = 0; nf < 8; nf++)
                        MMA(acc[mf][nf], ah[mf], bb[nf]);
            }
        }
        __syncthreads();
    }

    const int g = lane >> 2, t4 = lane & 3;
    #pragma unroll
    for (int mf = 0; mf < 4; mf++) {
        const int r = m0 + warp_m * 64 + mf * 16 + g;
        #pragma unroll
        for (int nf = 0; nf < 8; nf++) {
            const int c = n0 + warp_n * 64 + nf * 8 + t4 * 2;
            float2 v0 = make_float2(acc[mf][nf][0], acc[mf][nf][1]);
            float2 v1 = make_float2(acc[mf][nf][2], acc[mf][nf][3]);
            *reinterpret_cast<float2*>(C + (size_t)r * N + c) = v0;
            *reinterpret_cast<float2*>(C + (size_t)(r + 8) * N + c) = v1;
        }
    }
}

// ---------------------------------------------------------------------------
extern "C" void kernel_launch(void* const* d_in, const int* in_sizes, int n_in,
                              void* d_out, int out_size) {
    const float* x = (const float*)d_in[0];
    const float* w = (const float*)d_in[1];
    float* out = (float*)d_out;

    float *inv, *P;
    cudaGetSymbolAddress((void**)&inv, g_inv);
    cudaGetSymbolAddress((void**)&P, g_P);
    f16 *nh, *yh, *yl, *wh, *gh, *gl, *hh, *hl;
    cudaGetSymbolAddress((void**)&nh, g_nh);
    cudaGetSymbolAddress((void**)&yh, g_yh); cudaGetSymbolAddress((void**)&yl, g_yl);
    cudaGetSymbolAddress((void**)&wh, g_wh);
    cudaGetSymbolAddress((void**)&gh, g_gh); cudaGetSymbolAddress((void**)&gl, g_gl);
    cudaGetSymbolAddress((void**)&hh, g_hh); cudaGetSymbolAddress((void**)&hl, g_hl);

    cudaFuncSetAttribute(gemm_f16<1, 1>, cudaFuncAttributeMaxDynamicSharedMemorySize, 2 * 3 * TILE_PB);
    cudaFuncSetAttribute(gemm_f16<0, 1>, cudaFuncAttributeMaxDynamicSharedMemorySize, 2 * 3 * TILE_PB);
    cudaFuncSetAttribute(gemm_f16<0, 0>, cudaFuncAttributeMaxDynamicSharedMemorySize, 2 * 2 * TILE_PB);

    rownorm_inv<<<NROWS, 256>>>(x, inv);
    conv_x<<<dim3(DIM / 32, NROWS / 32), dim3(32, 8)>>>(x, inv, nh, yh, yl);
    conv_w<<<dim3(DIM / 32, DIM / 32), dim3(32, 8)>>>(w, wh);

    // G = y^T @ y (symmetric), 2-pass: 36 tri blocks x split-K 8 = 288 CTAs
    gemm_f16<1, 1><<<dim3(36, 1, 8), 128, 2 * 3 * TILE_PB>>>(
        yh, yh, yl, P, (size_t)DIM * DIM, DIM, NROWS, NROWS / 8);
    combine_tri<<<dim3(16, 36), 256>>>(P, 8, gh, gl);

    // H^T = MM(W^T hi, G hi/lo), 2-pass: split-K=4 -> 256 CTAs
    gemm_f16<0, 1><<<dim3(8, 8, 4), 128, 2 * 3 * TILE_PB>>>(
        wh, gh, gl, P, (size_t)DIM * DIM, DIM, DIM, DIM / 4);
    combine_lin<<<DIM * DIM / 1024, 256>>>(P, 4, hh, hl);

    // out = MM(norm hi, H^T hi), SINGLE pass: 512 CTAs
    gemm_f16<0, 0><<<dim3(8, 64, 1), 128, 2 * 2 * TILE_PB>>>(
        nh, hh, nullptr, out, 0, DIM, DIM, DIM);
}

// round 15
// speedup vs baseline: 1.0654x; 1.0654x over previous
#include <cuda_runtime.h>
#include <cuda_fp16.h>
#include <cstdint>

// out = norm @ ((norm^T @ x) @ W),  norm = x / max(||x_row||, 1e-12)
// y = sqrt(inv)*x  =>  G = y^T @ y (symmetric).
// fp16 hi/lo split on m16n8k16 HMMA (fp32 acc), legacy-HMMA rate ceiling:
//   GEMM1 (G):   2-pass (yh*yh + yh*yl), triangle + mirror
//   GEMM2 (H):   1-pass (W hi x G hi)
//   GEMM3 (out): 1-pass (norm hi x H hi)
// Error budget ~4.3e-4 vs 1e-3 gate.

#define NROWS 8192
#define DIM   1024
typedef __half f16;

// ---------------- scratch (device globals; no allocation allowed) ----------
__device__ float g_inv[NROWS];
__device__ f16 g_nh[NROWS * DIM];                       // norm hi, row-major
__device__ f16 g_yh[DIM * NROWS], g_yl[DIM * NROWS];    // y^T hi/lo [1024,8192]
__device__ f16 g_wh[DIM * DIM];                         // W^T hi
__device__ f16 g_gh[DIM * DIM];                         // G hi
__device__ f16 g_hh[DIM * DIM];                         // H^T hi
__device__ float g_P[8 * DIM * DIM];                    // split-K partials

__constant__ int2 c_tri[36] = {
    {0,0},{1,0},{1,1},{2,0},{2,1},{2,2},{3,0},{3,1},{3,2},{3,3},
    {4,0},{4,1},{4,2},{4,3},{4,4},{5,0},{5,1},{5,2},{5,3},{5,4},
    {5,5},{6,0},{6,1},{6,2},{6,3},{6,4},{6,5},{6,6},{7,0},{7,1},
    {7,2},{7,3},{7,4},{7,5},{7,6},{7,7}
};

// ---------------- PTX helpers ----------------------------------------------
__device__ __forceinline__ uint32_t smem_u32(const void* p) {
    uint32_t a;
    asm("{ .reg .u64 t; cvta.to.shared.u64 t, %1; cvt.u32.u64 %0, t; }" : "=r"(a) : "l"(p));
    return a;
}

#define CP16(saddr, gptr) \
    asm volatile("cp.async.cg.shared.global [%0], [%1], 16;" :: "r"(saddr), "l"(gptr))
#define CP_COMMIT() asm volatile("cp.async.commit_group;" ::: "memory")
#define CP_WAIT(n)  asm volatile("cp.async.wait_group %0;" :: "n"(n) : "memory")

#define LDSM4(r, addr) \
    asm volatile("ldmatrix.sync.aligned.m8n8.x4.shared.b16 {%0,%1,%2,%3}, [%4];" \
        : "=r"((r)[0]), "=r"((r)[1]), "=r"((r)[2]), "=r"((r)[3]) : "r"(addr))

#define MMA(c, a, b) \
    asm volatile("mma.sync.aligned.m16n8k16.row.col.f32.f16.f16.f32 " \
        "{%0,%1,%2,%3}, {%4,%5,%6,%7}, {%8,%9}, {%0,%1,%2,%3};" \
        : "+f"((c)[0]), "+f"((c)[1]), "+f"((c)[2]), "+f"((c)[3]) \
        : "r"((a)[0]), "r"((a)[1]), "r"((a)[2]), "r"((a)[3]), "r"((b)[0]), "r"((b)[1]))

// ---------------- small kernels --------------------------------------------
__global__ void rownorm_inv(const float* __restrict__ x, float* __restrict__ inv) {
    const int row = blockIdx.x;
    float4 v = reinterpret_cast<const float4*>(x + (size_t)row * DIM)[threadIdx.x];
    float s = v.x * v.x + v.y * v.y + v.z * v.z + v.w * v.w;
    #pragma unroll
    for (int o = 16; o > 0; o >>= 1) s += __shfl_down_sync(0xFFFFFFFFu, s, o);
    __shared__ float ws[8];
    if ((threadIdx.x & 31) == 0) ws[threadIdx.x >> 5] = s;
    __syncthreads();
    if (threadIdx.x == 0) {
        float t = 0.f;
        #pragma unroll
        for (int i = 0; i < 8; i++) t += ws[i];
        inv[row] = 1.0f / fmaxf(sqrtf(t), 1e-12f);
    }
}

__device__ __forceinline__ void split_h(float v, f16& h, f16& l) {
    h = __float2half_rn(v);
    l = __float2half_rn(v - __half2float(h));
}

__global__ void conv_x(const float* __restrict__ x, const float* __restrict__ inv,
                       f16* __restrict__ nh,
                       f16* __restrict__ yh, f16* __restrict__ yl) {
    __shared__ float sy[32][33];
    const int c = blockIdx.x * 32 + threadIdx.x;
    const int r0 = blockIdx.y * 32;
    #pragma unroll
    for (int i = 0; i < 4; i++) {
        int rl = threadIdx.y + i * 8;
        int r = r0 + rl;
        float iv = inv[r];
        float v = x[(size_t)r * DIM + c];
        nh[(size_t)r * DIM + c] = __float2half_rn(v * iv);
        sy[rl][threadIdx.x] = v * sqrtf(iv);
    }
    __syncthreads();
    const int tr = r0 + threadIdx.x;
    #pragma unroll
    for (int i = 0; i < 4; i++) {
        int cl = threadIdx.y + i * 8;
        int tc = blockIdx.x * 32 + cl;
        f16 h, l;
        split_h(sy[threadIdx.x][cl], h, l);
        yh[(size_t)tc * NROWS + tr] = h;
        yl[(size_t)tc * NROWS + tr] = l;
    }
}

__global__ void conv_w(const float* __restrict__ w, f16* __restrict__ wh) {
    __shared__ float sw[32][33];
    const int c = blockIdx.x * 32 + threadIdx.x;
    const int r0 = blockIdx.y * 32;
    #pragma unroll
    for (int i = 0; i < 4; i++) {
        int rl = threadIdx.y + i * 8;
        sw[rl][threadIdx.x] = w[(size_t)(r0 + rl) * DIM + c];
    }
    __syncthreads();
    const int tr = r0 + threadIdx.x;
    #pragma unroll
    for (int i = 0; i < 4; i++) {
        int cl = threadIdx.y + i * 8;
        int tc = blockIdx.x * 32 + cl;
        wh[(size_t)tc * DIM + tr] = __float2half_rn(sw[threadIdx.x][cl]);
    }
}

// sum NP split-K partials of a triangle block -> G hi (mirrored), hi only
__global__ void combine_tri(const float* __restrict__ P, int np,
                            f16* __restrict__ hi) {
    const int2 bp = c_tri[blockIdx.y];
    const int idx = (blockIdx.x * 256 + threadIdx.x) * 4;
    const int R = bp.x * 128 + (idx >> 7);
    const int C = bp.y * 128 + (idx & 127);
    const size_t o = (size_t)R * DIM + C;
    float v[4] = {0.f, 0.f, 0.f, 0.f};
    for (int p = 0; p < np; p++) {
        float4 a = *reinterpret_cast<const float4*>(P + (size_t)p * DIM * DIM + o);
        v[0] += a.x; v[1] += a.y; v[2] += a.z; v[3] += a.w;
    }
    f16 h[4];
    #pragma unroll
    for (int j = 0; j < 4; j++) h[j] = __float2half_rn(v[j]);
    *reinterpret_cast<uint2*>(hi + o) = *reinterpret_cast<const uint2*>(h);
    if (bp.x != bp.y) {
        #pragma unroll
        for (int j = 0; j < 4; j++) hi[(size_t)(C + j) * DIM + R] = h[j];
    }
}

// sum NP split-K partials (linear) -> hi only
__global__ void combine_lin(const float* __restrict__ P, int np,
                            f16* __restrict__ hi) {
    const int i = (blockIdx.x * 256 + threadIdx.x) * 4;
    float v[4] = {0.f, 0.f, 0.f, 0.f};
    for (int p = 0; p < np; p++) {
        float4 a = *reinterpret_cast<const float4*>(P + (size_t)p * DIM * DIM + i);
        v[0] += a.x; v[1] += a.y; v[2] += a.z; v[3] += a.w;
    }
    f16 h[4];
    #pragma unroll
    for (int j = 0; j < 4; j++) h[j] = __float2half_rn(v[j]);
    *reinterpret_cast<uint2*>(hi + i) = *reinterpret_cast<const uint2*>(h);
}

// ---------------- fp16 HMMA GEMM: C[m,n] = sum_k A[m,k]*B[n,k] --------------
// CTA 128x128, BK=32, 4 warps (2m x 2n), warp tile 64x64.
// PASS2=1: Bh+Bl two-pass. PASS2=0: Bh single pass.
#define TILE_PB  10240                // 128 * 80

template <int TRI, int PASS2>
__global__ __launch_bounds__(128, 2)
void gemm_f16(const f16* __restrict__ Ah,
              const f16* __restrict__ Bh, const f16* __restrict__ Bl,
              float* __restrict__ Cbase, size_t cplane,
              int N, int ldk, int ksplit) {
    constexpr int NT = PASS2 ? 3 : 2;
    constexpr int STAGE = NT * TILE_PB;
    extern __shared__ char smem[];
    const uint32_t su = smem_u32(smem);
    const int tid = threadIdx.x;
    const int lane = tid & 31;
    const int wid = tid >> 5;
    const int warp_m = wid & 1;
    const int warp_n = wid >> 1;
    int m0, n0;
    if (TRI) {
        const int2 bp = c_tri[blockIdx.x];
        m0 = bp.x * 128; n0 = bp.y * 128;
    } else {
        m0 = blockIdx.y * 128; n0 = blockIdx.x * 128;
    }
    const int k0 = blockIdx.z * ksplit;
    float* C = Cbase + (size_t)blockIdx.z * cplane;

    float acc[4][8][4];
    #pragma unroll
    for (int i = 0; i < 4; i++)
        #pragma unroll
        for (int j = 0; j < 8; j++)
            #pragma unroll
            for (int q = 0; q < 4; q++) acc[i][j][q] = 0.f;

    const uint32_t a_off = (uint32_t)(warp_m * 64 + (lane & 15)) * 80 + ((lane >> 4) << 4);
    const uint32_t b_off = (uint32_t)(warp_n * 64 + ((lane >> 4) << 3) + (lane & 7)) * 80
                         + (((lane >> 3) & 1) << 4);

    auto stage_load = [&](uint32_t s_stage, int k) {
        #pragma unroll
        for (int i = 0; i < 4; i++) {
            const int idx = tid + i * 128;
            const int row = idx >> 2;
            const int cb = (idx & 3) * 16;
            const uint32_t so = s_stage + row * 80 + cb;
            const size_t goA = ((size_t)(m0 + row) * ldk + k) * 2 + cb;
            const size_t goB = ((size_t)(n0 + row) * ldk + k) * 2 + cb;
            CP16(so,           (const char*)Ah + goA);
            CP16(so + TILE_PB, (const char*)Bh + goB);
            if (PASS2) CP16(so + 2 * TILE_PB, (const char*)Bl + goB);
        }
    };

    const int NIT = ksplit / 32;
    stage_load(su, k0);
    CP_COMMIT();

    for (int it = 0; it < NIT; it++) {
        if (it + 1 < NIT) {
            stage_load(su + ((it + 1) & 1) * STAGE, k0 + (it + 1) * 32);
            CP_COMMIT();
            CP_WAIT(1);
        } else {
            CP_WAIT(0);
        }
        __syncthreads();

        const uint32_t st = su + (it & 1) * STAGE;
        const uint32_t a_h = st + a_off;
        const uint32_t b_h = st + TILE_PB + b_off;
        const uint32_t b_l = b_h + TILE_PB;

        #pragma unroll
        for (int ks = 0; ks < 2; ks++) {
            uint32_t ah[4][4], bb[8][2];
            #pragma unroll
            for (int mf = 0; mf < 4; mf++) LDSM4(ah[mf], a_h + mf * 1280 + ks * 32);
            #pragma unroll
            for (int bg = 0; bg < 4; bg++) {
                uint32_t t[4];
                LDSM4(t, b_h + bg * 1280 + ks * 32);
                bb[2 * bg][0] = t[0]; bb[2 * bg][1] = t[1];
                bb[2 * bg + 1][0] = t[2]; bb[2 * bg + 1][1] = t[3];
            }
            #pragma unroll
            for (int mf = 0; mf < 4; mf++)
                #pragma unroll
                for (int nf = 0; nf < 8; nf++)
                    MMA(acc[mf][nf], ah[mf], bb[nf]);
            if (PASS2) {
                #pragma unroll
                for (int bg = 0; bg < 4; bg++) {
                    uint32_t t[4];
                    LDSM4(t, b_l + bg * 1280 + ks * 32);
                    bb[2 * bg][0] = t[0]; bb[2 * bg][1] = t[1];
                    bb[2 * bg + 1][0] = t[2]; bb[2 * bg + 1][1] = t[3];
                }
                #pragma unroll
                for (int mf = 0; mf < 4; mf++)
                    #pragma unroll
                    for (int nf = 0; nf < 8; nf++)
                        MMA(acc[mf][nf], ah[mf], bb[nf]);
            }
        }
        __syncthreads();
    }

    const int g = lane >> 2, t4 = lane & 3;
    #pragma unroll
    for (int mf = 0; mf < 4; mf++) {
        const int r = m0 + warp_m * 64 + mf * 16 + g;
        #pragma unroll
        for (int nf = 0; nf < 8; nf++) {
            const int c = n0 + warp_n * 64 + nf * 8 + t4 * 2;
            float2 v0 = make_float2(acc[mf][nf][0], acc[mf][nf][1]);
            float2 v1 = make_float2(acc[mf][nf][2], acc[mf][nf][3]);
            *reinterpret_cast<float2*>(C + (size_t)r * N + c) = v0;
            *reinterpret_cast<float2*>(C + (size_t)(r + 8) * N + c) = v1;
        }
    }
}

// ---------------------------------------------------------------------------
extern "C" void kernel_launch(void* const* d_in, const int* in_sizes, int n_in,
                              void* d_out, int out_size) {
    const float* x = (const float*)d_in[0];
    const float* w = (const float*)d_in[1];
    float* out = (float*)d_out;

    float *inv, *P;
    cudaGetSymbolAddress((void**)&inv, g_inv);
    cudaGetSymbolAddress((void**)&P, g_P);
    f16 *nh, *yh, *yl, *wh, *gh, *hh;
    cudaGetSymbolAddress((void**)&nh, g_nh);
    cudaGetSymbolAddress((void**)&yh, g_yh); cudaGetSymbolAddress((void**)&yl, g_yl);
    cudaGetSymbolAddress((void**)&wh, g_wh);
    cudaGetSymbolAddress((void**)&gh, g_gh);
    cudaGetSymbolAddress((void**)&hh, g_hh);

    cudaFuncSetAttribute(gemm_f16<1, 1>, cudaFuncAttributeMaxDynamicSharedMemorySize, 2 * 3 * TILE_PB);
    cudaFuncSetAttribute(gemm_f16<0, 0>, cudaFuncAttributeMaxDynamicSharedMemorySize, 2 * 2 * TILE_PB);

    rownorm_inv<<<NROWS, 256>>>(x, inv);
    conv_x<<<dim3(DIM / 32, NROWS / 32), dim3(32, 8)>>>(x, inv, nh, yh, yl);
    conv_w<<<dim3(DIM / 32, DIM / 32), dim3(32, 8)>>>(w, wh);

    // G = y^T @ y (symmetric), 2-pass: 36 tri blocks x split-K 8 = 288 CTAs
    gemm_f16<1, 1><<<dim3(36, 1, 8), 128, 2 * 3 * TILE_PB>>>(
        yh, yh, yl, P, (size_t)DIM * DIM, DIM, NROWS, NROWS / 8);
    combine_tri<<<dim3(16, 36), 256>>>(P, 8, gh);

    // H^T = MM(W^T hi, G hi), SINGLE pass: split-K=4 -> 256 CTAs
    gemm_f16<0, 0><<<dim3(8, 8, 4), 128, 2 * 2 * TILE_PB>>>(
        wh, gh, nullptr, P, (size_t)DIM * DIM, DIM, DIM, DIM / 4);
    combine_lin<<<DIM * DIM / 1024, 256>>>(P, 4, hh);

    // out = MM(norm hi, H^T hi), SINGLE pass: 512 CTAs
    gemm_f16<0, 0><<<dim3(8, 64, 1), 128, 2 * 2 * TILE_PB>>>(
        nh, hh, nullptr, out, 0, DIM, DIM, DIM);
}

// round 17
// speedup vs baseline: 1.1906x; 1.1175x over previous
#include <cuda_runtime.h>
#include <cuda_fp16.h>
#include <cstdint>

// out = norm @ ((norm^T @ x) @ W),  norm = x / max(||x_row||, 1e-12)
// y = sqrt(inv)*x  =>  G = y^T @ y (symmetric).
// All GEMMs single-pass fp16-hi on m16n8k16 HMMA (fp32 acc).
// Measured error budget: ~1.8e-4 per dropped lo-term, 6 terms -> ~4.5e-4 vs 1e-3.

#define NROWS 8192
#define DIM   1024
typedef __half f16;

// ---------------- scratch (device globals; no allocation allowed) ----------
__device__ float g_inv[NROWS];
__device__ f16 g_nh[NROWS * DIM];                       // norm hi, row-major
__device__ f16 g_yh[DIM * NROWS];                       // y^T hi [1024,8192]
__device__ f16 g_wh[DIM * DIM];                         // W^T hi
__device__ f16 g_gh[DIM * DIM];                         // G hi
__device__ f16 g_hh[DIM * DIM];                         // H^T hi
__device__ float g_P[4 * DIM * DIM];                    // split-K partials

__constant__ int2 c_tri[36] = {
    {0,0},{1,0},{1,1},{2,0},{2,1},{2,2},{3,0},{3,1},{3,2},{3,3},
    {4,0},{4,1},{4,2},{4,3},{4,4},{5,0},{5,1},{5,2},{5,3},{5,4},
    {5,5},{6,0},{6,1},{6,2},{6,3},{6,4},{6,5},{6,6},{7,0},{7,1},
    {7,2},{7,3},{7,4},{7,5},{7,6},{7,7}
};

// ---------------- PTX helpers ----------------------------------------------
__device__ __forceinline__ uint32_t smem_u32(const void* p) {
    uint32_t a;
    asm("{ .reg .u64 t; cvta.to.shared.u64 t, %1; cvt.u32.u64 %0, t; }" : "=r"(a) : "l"(p));
    return a;
}

#define CP16(saddr, gptr) \
    asm volatile("cp.async.cg.shared.global [%0], [%1], 16;" :: "r"(saddr), "l"(gptr))
#define CP_COMMIT() asm volatile("cp.async.commit_group;" ::: "memory")
#define CP_WAIT(n)  asm volatile("cp.async.wait_group %0;" :: "n"(n) : "memory")

#define LDSM4(r, addr) \
    asm volatile("ldmatrix.sync.aligned.m8n8.x4.shared.b16 {%0,%1,%2,%3}, [%4];" \
        : "=r"((r)[0]), "=r"((r)[1]), "=r"((r)[2]), "=r"((r)[3]) : "r"(addr))

#define MMA(c, a, b) \
    asm volatile("mma.sync.aligned.m16n8k16.row.col.f32.f16.f16.f32 " \
        "{%0,%1,%2,%3}, {%4,%5,%6,%7}, {%8,%9}, {%0,%1,%2,%3};" \
        : "+f"((c)[0]), "+f"((c)[1]), "+f"((c)[2]), "+f"((c)[3]) \
        : "r"((a)[0]), "r"((a)[1]), "r"((a)[2]), "r"((a)[3]), "r"((b)[0]), "r"((b)[1]))

// ---------------- small kernels --------------------------------------------
__global__ void rownorm_inv(const float* __restrict__ x, float* __restrict__ inv) {
    const int row = blockIdx.x;
    float4 v = reinterpret_cast<const float4*>(x + (size_t)row * DIM)[threadIdx.x];
    float s = v.x * v.x + v.y * v.y + v.z * v.z + v.w * v.w;
    #pragma unroll
    for (int o = 16; o > 0; o >>= 1) s += __shfl_down_sync(0xFFFFFFFFu, s, o);
    __shared__ float ws[8];
    if ((threadIdx.x & 31) == 0) ws[threadIdx.x >> 5] = s;
    __syncthreads();
    if (threadIdx.x == 0) {
        float t = 0.f;
        #pragma unroll
        for (int i = 0; i < 8; i++) t += ws[i];
        inv[row] = 1.0f / fmaxf(sqrtf(t), 1e-12f);
    }
}

// x -> norm hi (row-major), y^T hi (K-major); y = sqrt(inv)*x
__global__ void conv_x(const float* __restrict__ x, const float* __restrict__ inv,
                       f16* __restrict__ nh, f16* __restrict__ yh) {
    __shared__ float sy[32][33];
    const int c = blockIdx.x * 32 + threadIdx.x;
    const int r0 = blockIdx.y * 32;
    #pragma unroll
    for (int i = 0; i < 4; i++) {
        int rl = threadIdx.y + i * 8;
        int r = r0 + rl;
        float iv = inv[r];
        float v = x[(size_t)r * DIM + c];
        nh[(size_t)r * DIM + c] = __float2half_rn(v * iv);
        sy[rl][threadIdx.x] = v * sqrtf(iv);
    }
    __syncthreads();
    const int tr = r0 + threadIdx.x;
    #pragma unroll
    for (int i = 0; i < 4; i++) {
        int cl = threadIdx.y + i * 8;
        int tc = blockIdx.x * 32 + cl;
        yh[(size_t)tc * NROWS + tr] = __float2half_rn(sy[threadIdx.x][cl]);
    }
}

__global__ void conv_w(const float* __restrict__ w, f16* __restrict__ wh) {
    __shared__ float sw[32][33];
    const int c = blockIdx.x * 32 + threadIdx.x;
    const int r0 = blockIdx.y * 32;
    #pragma unroll
    for (int i = 0; i < 4; i++) {
        int rl = threadIdx.y + i * 8;
        sw[rl][threadIdx.x] = w[(size_t)(r0 + rl) * DIM + c];
    }
    __syncthreads();
    const int tr = r0 + threadIdx.x;
    #pragma unroll
    for (int i = 0; i < 4; i++) {
        int cl = threadIdx.y + i * 8;
        int tc = blockIdx.x * 32 + cl;
        wh[(size_t)tc * DIM + tr] = __float2half_rn(sw[threadIdx.x][cl]);
    }
}

// sum NP split-K partials of a triangle block -> G hi (mirrored)
__global__ void combine_tri(const float* __restrict__ P, int np,
                            f16* __restrict__ hi) {
    const int2 bp = c_tri[blockIdx.y];
    const int idx = (blockIdx.x * 256 + threadIdx.x) * 4;
    const int R = bp.x * 128 + (idx >> 7);
    const int C = bp.y * 128 + (idx & 127);
    const size_t o = (size_t)R * DIM + C;
    float v[4] = {0.f, 0.f, 0.f, 0.f};
    for (int p = 0; p < np; p++) {
        float4 a = *reinterpret_cast<const float4*>(P + (size_t)p * DIM * DIM + o);
        v[0] += a.x; v[1] += a.y; v[2] += a.z; v[3] += a.w;
    }
    f16 h[4];
    #pragma unroll
    for (int j = 0; j < 4; j++) h[j] = __float2half_rn(v[j]);
    *reinterpret_cast<uint2*>(hi + o) = *reinterpret_cast<const uint2*>(h);
    if (bp.x != bp.y) {
        #pragma unroll
        for (int j = 0; j < 4; j++) hi[(size_t)(C + j) * DIM + R] = h[j];
    }
}

__global__ void combine_lin(const float* __restrict__ P, int np,
                            f16* __restrict__ hi) {
    const int i = (blockIdx.x * 256 + threadIdx.x) * 4;
    float v[4] = {0.f, 0.f, 0.f, 0.f};
    for (int p = 0; p < np; p++) {
        float4 a = *reinterpret_cast<const float4*>(P + (size_t)p * DIM * DIM + i);
        v[0] += a.x; v[1] += a.y; v[2] += a.z; v[3] += a.w;
    }
    f16 h[4];
    #pragma unroll
    for (int j = 0; j < 4; j++) h[j] = __float2half_rn(v[j]);
    *reinterpret_cast<uint2*>(hi + i) = *reinterpret_cast<const uint2*>(h);
}

// ---------------- fp16 HMMA GEMM: C[m,n] = sum_k A[m,k]*B[n,k] --------------
// CTA 128x128, BK=32, 4 warps (2m x 2n), warp tile 64x64, single pass.
#define TILE_PB  10240                // 128 * 80
#define STAGE_B  (2 * TILE_PB)        // Ah, Bh
#define SMEM_DYN (2 * STAGE_B)        // 40960

template <int TRI>
__global__ __launch_bounds__(128, 2)
void gemm_f16(const f16* __restrict__ Ah, const f16* __restrict__ Bh,
              float* __restrict__ Cbase, size_t cplane,
              int N, int ldk, int ksplit) {
    extern __shared__ char smem[];
    const uint32_t su = smem_u32(smem);
    const int tid = threadIdx.x;
    const int lane = tid & 31;
    const int wid = tid >> 5;
    const int warp_m = wid & 1;
    const int warp_n = wid >> 1;
    int m0, n0;
    if (TRI) {
        const int2 bp = c_tri[blockIdx.x];
        m0 = bp.x * 128; n0 = bp.y * 128;
    } else {
        m0 = blockIdx.y * 128; n0 = blockIdx.x * 128;
    }
    const int k0 = blockIdx.z * ksplit;
    float* C = Cbase + (size_t)blockIdx.z * cplane;

    float acc[4][8][4];
    #pragma unroll
    for (int i = 0; i < 4; i++)
        #pragma unroll
        for (int j = 0; j < 8; j++)
            #pragma unroll
            for (int q = 0; q < 4; q++) acc[i][j][q] = 0.f;

    const uint32_t a_off = (uint32_t)(warp_m * 64 + (lane & 15)) * 80 + ((lane >> 4) << 4);
    const uint32_t b_off = (uint32_t)(warp_n * 64 + ((lane >> 4) << 3) + (lane & 7)) * 80
                         + (((lane >> 3) & 1) << 4);

    auto stage_load = [&](uint32_t s_stage, int k) {
        #pragma unroll
        for (int i = 0; i < 4; i++) {
            const int idx = tid + i * 128;
            const int row = idx >> 2;
            const int cb = (idx & 3) * 16;
            const uint32_t so = s_stage + row * 80 + cb;
            const size_t goA = ((size_t)(m0 + row) * ldk + k) * 2 + cb;
            const size_t goB = ((size_t)(n0 + row) * ldk + k) * 2 + cb;
            CP16(so,           (const char*)Ah + goA);
            CP16(so + TILE_PB, (const char*)Bh + goB);
        }
    };

    const int NIT = ksplit / 32;
    stage_load(su, k0);
    CP_COMMIT();

    for (int it = 0; it < NIT; it++) {
        if (it + 1 < NIT) {
            stage_load(su + ((it + 1) & 1) * STAGE_B, k0 + (it + 1) * 32);
            CP_COMMIT();
            CP_WAIT(1);
        } else {
            CP_WAIT(0);
        }
        __syncthreads();

        const uint32_t st = su + (it & 1) * STAGE_B;
        const uint32_t a_h = st + a_off;
        const uint32_t b_h = st + TILE_PB + b_off;

        #pragma unroll
        for (int ks = 0; ks < 2; ks++) {
            uint32_t ah[4][4], bb[8][2];
            #pragma unroll
            for (int mf = 0; mf < 4; mf++) LDSM4(ah[mf], a_h + mf * 1280 + ks * 32);
            #pragma unroll
            for (int bg = 0; bg < 4; bg++) {
                uint32_t t[4];
                LDSM4(t, b_h + bg * 1280 + ks * 32);
                bb[2 * bg][0] = t[0]; bb[2 * bg][1] = t[1];
                bb[2 * bg + 1][0] = t[2]; bb[2 * bg + 1][1] = t[3];
            }
            #pragma unroll
            for (int mf = 0; mf < 4; mf++)
                #pragma unroll
                for (int nf = 0; nf < 8; nf++)
                    MMA(acc[mf][nf], ah[mf], bb[nf]);
        }
        __syncthreads();
    }

    const int g = lane >> 2, t4 = lane & 3;
    #pragma unroll
    for (int mf = 0; mf < 4; mf++) {
        const int r = m0 + warp_m * 64 + mf * 16 + g;
        #pragma unroll
        for (int nf = 0; nf < 8; nf++) {
            const int c = n0 + warp_n * 64 + nf * 8 + t4 * 2;
            float2 v0 = make_float2(acc[mf][nf][0], acc[mf][nf][1]);
            float2 v1 = make_float2(acc[mf][nf][2], acc[mf][nf][3]);
            *reinterpret_cast<float2*>(C + (size_t)r * N + c) = v0;
            *reinterpret_cast<float2*>(C + (size_t)(r + 8) * N + c) = v1;
        }
    }
}

// ---------------------------------------------------------------------------
extern "C" void kernel_launch(void* const* d_in, const int* in_sizes, int n_in,
                              void* d_out, int out_size) {
    const float* x = (const float*)d_in[0];
    const float* w = (const float*)d_in[1];
    float* out = (float*)d_out;

    float *inv, *P;
    cudaGetSymbolAddress((void**)&inv, g_inv);
    cudaGetSymbolAddress((void**)&P, g_P);
    f16 *nh, *yh, *wh, *gh, *hh;
    cudaGetSymbolAddress((void**)&nh, g_nh);
    cudaGetSymbolAddress((void**)&yh, g_yh);
    cudaGetSymbolAddress((void**)&wh, g_wh);
    cudaGetSymbolAddress((void**)&gh, g_gh);
    cudaGetSymbolAddress((void**)&hh, g_hh);

    cudaFuncSetAttribute(gemm_f16<1>, cudaFuncAttributeMaxDynamicSharedMemorySize, SMEM_DYN);
    cudaFuncSetAttribute(gemm_f16<0>, cudaFuncAttributeMaxDynamicSharedMemorySize, SMEM_DYN);

    rownorm_inv<<<NROWS, 256>>>(x, inv);
    conv_x<<<dim3(DIM / 32, NROWS / 32), dim3(32, 8)>>>(x, inv, nh, yh);
    conv_w<<<dim3(DIM / 32, DIM / 32), dim3(32, 8)>>>(w, wh);

    // G = y^T @ y (symmetric), 1-pass: 36 tri blocks x split-K 4 = 144 CTAs
    gemm_f16<1><<<dim3(36, 1, 4), 128, SMEM_DYN>>>(
        yh, yh, P, (size_t)DIM * DIM, DIM, NROWS, NROWS / 4);
    combine_tri<<<dim3(16, 36), 256>>>(P, 4, gh);

    // H^T = MM(W^T hi, G hi), 1-pass: split-K=4 -> 256 CTAs
    gemm_f16<0><<<dim3(8, 8, 4), 128, SMEM_DYN>>>(
        wh, gh, P, (size_t)DIM * DIM, DIM, DIM, DIM / 4);
    combine_lin<<<DIM * DIM / 1024, 256>>>(P, 4, hh);

    // out = MM(norm hi, H^T hi), 1-pass: 512 CTAs
    gemm_f16<0><<<dim3(8, 64, 1), 128, SMEM_DYN>>>(
        nh, hh, out, 0, DIM, DIM, DIM);
}